// round 14
// baseline (speedup 1.0000x reference)
#include <cuda_runtime.h>

#define FULL 0xffffffffu
#define BATCH 32768

// Fused VQC (math validated R7-R13): out_i = K_i * sum_T D_i[T] * sigma_T.
// R14: R11 geometry (128 blocks x 512 threads, warp-specialized), with all
// sD-independent work hoisted ahead of the block barrier:
//   role 0 (warps 0-7): LDG + 8 sincos + ALL sigma monomials + K products
//     pre-barrier; publishes prefabricated p8/p6 outer tables + sz6/sz7 +
//     K5-K7; post-barrier only LDS(sD)+FMA chains for out0-4.
//   role 1 (warps 8-15): warp w builds D table (w-8) (barrier-free FWHT);
//     post-barrier loads prefab tables and runs out5-7 accumulations.

__global__ __launch_bounds__(512) void vqc_fused(const float* __restrict__ inputs,
                                                 const float* __restrict__ weights,
                                                 float* __restrict__ out) {
    __shared__ float sD[8][256];
    __shared__ float s_p8[7][256];   // {sz4, sz2, s42, sz0, s40, s20, s420}
    __shared__ float s_p6[7][256];   // {sz5, sz3, m53, sz1, m51, m31, m531}
    __shared__ float s_x[5][256];    // {sz6, sz7, K5, K6, K7}

    const int tid  = threadIdx.x;
    const int lane = tid & 31;
    const int wid  = tid >> 5;
    const int role = tid >> 8;          // warp-uniform
    const int eloc = tid & 255;
    const int e    = blockIdx.x * 256 + eloc;

    // role-0 register state carried across the barrier
    float sz0, cz0, sz1, cz1, sz2, cz2, sz3, cz3, sz4, cz4, sz5, cz5, sz6, cz6, sz7, cz7;
    float q21, q32, q30, q43, q41, s0C, q52, q50, qAC, q40;
    float s42r, s20r, m31r;
    float Ko2, Ke2, Ke3;

    if (role == 0) {
        // ---- full-element sincos pipeline ----
        const float4 z0 = *reinterpret_cast<const float4*>(inputs + e * 8);
        const float4 z1 = *reinterpret_cast<const float4*>(inputs + e * 8 + 4);
        __sincosf(z0.x, &sz0, &cz0);  __sincosf(z0.y, &sz1, &cz1);
        __sincosf(z0.z, &sz2, &cz2);  __sincosf(z0.w, &sz3, &cz3);
        __sincosf(z1.x, &sz4, &cz4);  __sincosf(z1.y, &sz5, &cz5);
        __sincosf(z1.z, &sz6, &cz6);  __sincosf(z1.w, &sz7, &cz7);

        // outer-product tables for role 1 (prefabricated)
        float s42 = sz4 * sz2, s40 = sz4 * sz0, s20 = sz2 * sz0, s420 = s42 * sz0;
        float m53 = sz5 * sz3, m51 = sz5 * sz1, m31 = sz3 * sz1, m531 = m53 * sz1;
        s_p8[0][eloc] = sz4; s_p8[1][eloc] = sz2; s_p8[2][eloc] = s42;
        s_p8[3][eloc] = sz0; s_p8[4][eloc] = s40; s_p8[5][eloc] = s20;
        s_p8[6][eloc] = s420;
        s_p6[0][eloc] = sz5; s_p6[1][eloc] = sz3; s_p6[2][eloc] = m53;
        s_p6[3][eloc] = sz1; s_p6[4][eloc] = m51; s_p6[5][eloc] = m31;
        s_p6[6][eloc] = m531;

        float K5 = cz1 * cz3 * cz5;
        float K6 = cz0 * cz2 * cz4 * cz6;
        float K7 = K5 * cz7;
        s_x[0][eloc] = sz6; s_x[1][eloc] = sz7;
        s_x[2][eloc] = K5;  s_x[3][eloc] = K6;  s_x[4][eloc] = K7;

        // own monomials / K products (pre-barrier; consumed post-barrier)
        q21 = sz2 * sz1;
        q32 = sz3 * sz2;  q30 = sz3 * sz0;
        q43 = sz4 * sz3;  q41 = sz4 * sz1;
        s0C = sz5 * sz4;  q52 = sz5 * sz2;  q50 = sz5 * sz0;
        qAC = s0C * s20;  q40 = s40;
        s42r = s42; s20r = s20; m31r = m31;
        Ke2 = cz0 * cz2;  Ko2 = cz1 * cz3;  Ke3 = Ke2 * cz4;
    } else {
        // ---- FWHT pipeline: warp (wid-8) builds table D_(wid-8) ----
        const int i  = wid - 8;
        const int sh = 6 - 2 * (i >> 1);
        const int A  = (((0xAA >> sh) << sh) >> (i & 1));
        const int msk[16]  = {0x01,0x03,0x06,0x0C,0x18,0x30,0x60,0xC0,
                              0x01,0x02,0x05,0x0A,0x14,0x28,0x50,0xA0};
        const int widx[16] = {7,6,5,4,3,2,1,0, 15,14,13,12,11,10,9,8};
        float th[16];
#pragma unroll
        for (int j = 0; j < 16; j++) th[j] = __ldg(&weights[widx[j]]);

        float C[8];
#pragma unroll
        for (int r = 0; r < 8; r++) {
            const int w = r * 32 + lane;
            float d = 0.0f;
#pragma unroll
            for (int jj = 0; jj < 16; jj++) {
                if (__popc(msk[jj] & A) & 1)                 // warp-uniform
                    d += (__popc(msk[jj] & w) & 1) ? -th[jj] : th[jj];
            }
            C[r] = __cosf(d);
        }
#pragma unroll
        for (int sb = 1; sb < 8; sb <<= 1) {
            float t[8];
#pragma unroll
            for (int r = 0; r < 8; r++)
                t[r] = (r & sb) ? (C[r ^ sb] - C[r]) : (C[r] + C[r ^ sb]);
#pragma unroll
            for (int r = 0; r < 8; r++) C[r] = t[r];
        }
#pragma unroll
        for (int s = 1; s < 32; s <<= 1) {
            float sign = (lane & s) ? -1.0f : 1.0f;
#pragma unroll
            for (int r = 0; r < 8; r++) {
                float o = __shfl_xor_sync(FULL, C[r], s);
                C[r] = fmaf(sign, C[r], o);
            }
        }
#pragma unroll
        for (int r = 0; r < 8; r++)
            sD[i][r * 32 + lane] = C[r] * (1.0f / 256.0f);
    }
    __syncthreads();

    if (role == 0) {
        // ---- out0-4: pure LDS(sD) + FMA (monomials precomputed) ----
        float o0 = cz0 * fmaf(sD[0][0x60], q21, sD[0][0x00]);

        float o1 = fmaf(sD[1][0xA0], s20r, sD[1][0x00]);
        o1 = fmaf(sD[1][0x30], q32, o1);
        o1 = fmaf(sD[1][0x90], q30, o1);
        o1 *= cz1;

        float o2 = fmaf(sD[2][0x50], m31r, sD[2][0x00]);
        o2 = fmaf(sD[2][0x18], q43, o2);
        o2 = fmaf(sD[2][0x48], q41, o2);
        o2 *= Ke2;

        float o3 = fmaf(sD[3][0x28], s42r, sD[3][0x00]);
        o3 = fmaf(sD[3][0x0C], s0C, o3);
        o3 = fmaf(sD[3][0x24], q52, o3);
        o3 = fmaf(sD[3][0xA0], s20r, o3);
        o3 = fmaf(sD[3][0x84], q50, o3);
        o3 = fmaf(sD[3][0xAC], qAC, o3);
        o3 = fmaf(sD[3][0x88], q40, o3);
        o3 *= Ko2;

        // out4: comp(0xA8); inner sz7,sz6,sz5; outer p4 = {1,sz3,sz1,m31}
        float p4[4] = {1.0f, sz3, sz1, m31r};
        const int b4[4] = {0, 16, 64, 80};
        float acc4 = 0.0f;
#pragma unroll
        for (int g = 0; g < 4; g++) {
            float4 a = *reinterpret_cast<const float4*>(&sD[4][b4[g]]);
            float4 b = *reinterpret_cast<const float4*>(&sD[4][b4[g] + 4]);
            float lo = fmaf(a.y, sz7, a.x) + sz6 * fmaf(a.w, sz7, a.z);
            float hi = fmaf(b.y, sz7, b.x) + sz6 * fmaf(b.w, sz7, b.z);
            acc4 = fmaf(p4[g], fmaf(sz5, hi, lo), acc4);
        }
        float o4 = Ke3 * acc4;

        *reinterpret_cast<float4*>(out + e * 8) = make_float4(o0, o1, o2, o3);
        out[e * 8 + 4] = o4;
    } else {
        // ---- out5-7 from prefabricated tables (identical math to R9-R13) ----
        float p8[8], p6[8];
        p8[0] = 1.0f; p6[0] = 1.0f;
#pragma unroll
        for (int k = 0; k < 7; k++) { p8[k + 1] = s_p8[k][eloc]; p6[k + 1] = s_p6[k][eloc]; }
        const float sz6v = s_x[0][eloc], sz7v = s_x[1][eloc];
        const float K5 = s_x[2][eloc], K6 = s_x[3][eloc], K7 = s_x[4][eloc];

        const int b5[8] = {0, 8, 32, 40, 128, 136, 160, 168};
        float acc5 = 0.0f;
#pragma unroll
        for (int g = 0; g < 8; g++) {
            float4 a = *reinterpret_cast<const float4*>(&sD[5][b5[g]]);
            float inner = fmaf(a.y, sz7v, a.x) + sz6v * fmaf(a.w, sz7v, a.z);
            acc5 = fmaf(p8[g], inner, acc5);
        }
        const int b6[8] = {0, 4, 16, 20, 64, 68, 80, 84};
        float acc6 = 0.0f;
#pragma unroll
        for (int g = 0; g < 8; g++) {
            float2 a = *reinterpret_cast<const float2*>(&sD[6][b6[g]]);
            acc6 = fmaf(p6[g], fmaf(a.y, sz7v, a.x), acc6);
        }
        float acc7 = 0.0f;
#pragma unroll
        for (int g = 0; g < 8; g++) {
            float lo = sD[7][b5[g]];
            float hi = sD[7][b5[g] + 2];
            acc7 = fmaf(p8[g], fmaf(hi, sz6v, lo), acc7);
        }

        out[e * 8 + 5] = K5 * acc5;
        *reinterpret_cast<float2*>(out + e * 8 + 6) = make_float2(K6 * acc6, K7 * acc7);
    }
}

extern "C" void kernel_launch(void* const* d_in, const int* in_sizes, int n_in,
                              void* d_out, int out_size) {
    const float* inputs  = (const float*)d_in[0];   // (32768, 8) float32
    const float* weights = (const float*)d_in[1];   // (2, 8)     float32
    float* out = (float*)d_out;                     // (32768, 8) float32

    // 128 blocks x 512 threads (R11 geometry): warps 0-7 sincos+eval0-4,
    // warps 8-15 FWHT+eval5-7; all sD-independent work pre-barrier
    vqc_fused<<<BATCH / 256, 512>>>(inputs, weights, out);
}

// round 15
// speedup vs baseline: 1.0140x; 1.0140x over previous
#include <cuda_runtime.h>

#define FULL 0xffffffffu
#define BATCH 32768

// Fused VQC (math validated R7-R14): out_i = K_i * sum_T D_i[T] * sigma_T.
// R15 = R11 geometry (128 blocks x 512 threads, warp-specialized) with the
// FWHT delta-phase computed incrementally:
//   delta(w = r*32+lane) = d0(lane) - 2*F_r, where d0 is one 16-term signed
//   sum and F_r combines only the 6 masks touching w-bits 5..7
//   (0x30->tl[5], 0x60->tl[6], 0xC0->tl[7], 0x28->tl[13], 0x50->tl[14],
//    0xA0->tl[15]); parity groups h = msk>>5 in {1,2,3,5,6}:
//   F1=U1+U3+U5  F2=U2+U3+U6  F3=U1+U2+U5+U6  F4=U5+U6
//   F5=U1+U3+U6  F6=U2+U3+U5  F7=U1+U2        (U_h = sum of tl with that h)
// Replaces 128 predicated select-adds with ~40 adds per FWHT warp.

__global__ __launch_bounds__(512) void vqc_fused(const float* __restrict__ inputs,
                                                 const float* __restrict__ weights,
                                                 float* __restrict__ out) {
    __shared__ float sD[8][256];
    __shared__ float s_sz[8][256];
    __shared__ float s_K[3][256];

    const int tid  = threadIdx.x;
    const int lane = tid & 31;
    const int wid  = tid >> 5;
    const int role = tid >> 8;          // warp-uniform
    const int eloc = tid & 255;
    const int e    = blockIdx.x * 256 + eloc;

    float sz0, cz0, sz1, cz1, sz2, cz2, sz3, cz3, sz4, cz4, sz5, cz5, sz6, cz6, sz7, cz7;

    if (role == 0) {
        // ---- full-element sincos pipeline ----
        const float4 z0 = *reinterpret_cast<const float4*>(inputs + e * 8);
        const float4 z1 = *reinterpret_cast<const float4*>(inputs + e * 8 + 4);
        __sincosf(z0.x, &sz0, &cz0);  __sincosf(z0.y, &sz1, &cz1);
        __sincosf(z0.z, &sz2, &cz2);  __sincosf(z0.w, &sz3, &cz3);
        __sincosf(z1.x, &sz4, &cz4);  __sincosf(z1.y, &sz5, &cz5);
        __sincosf(z1.z, &sz6, &cz6);  __sincosf(z1.w, &sz7, &cz7);

        s_sz[0][eloc] = sz0; s_sz[1][eloc] = sz1; s_sz[2][eloc] = sz2; s_sz[3][eloc] = sz3;
        s_sz[4][eloc] = sz4; s_sz[5][eloc] = sz5; s_sz[6][eloc] = sz6; s_sz[7][eloc] = sz7;

        float K5 = cz1 * cz3 * cz5;
        float K6 = cz0 * cz2 * cz4 * cz6;
        float K7 = K5 * cz7;
        s_K[0][eloc] = K5; s_K[1][eloc] = K6; s_K[2][eloc] = K7;
    } else {
        // ---- FWHT pipeline: warp (wid-8) builds table D_(wid-8) ----
        const int i  = wid - 8;
        const int sh = 6 - 2 * (i >> 1);
        const int A  = (((0xAA >> sh) << sh) >> (i & 1));
        const int msk[16]  = {0x01,0x03,0x06,0x0C,0x18,0x30,0x60,0xC0,
                              0x01,0x02,0x05,0x0A,0x14,0x28,0x50,0xA0};
        const int widx[16] = {7,6,5,4,3,2,1,0, 15,14,13,12,11,10,9,8};

        // tl[j] = (j in S_i) ? eps_j(lane)*theta_j : 0
        float tl[16];
#pragma unroll
        for (int j = 0; j < 16; j++) {
            float th = __ldg(&weights[widx[j]]);
            bool inS = (__popc(msk[j] & A) & 1);             // warp-uniform
            float v  = (__popc(msk[j] & lane) & 1) ? -th : th;
            tl[j] = inS ? v : 0.0f;
        }
        // d0 = sum over all j
        float d0 = 0.0f;
#pragma unroll
        for (int j = 0; j < 16; j++) d0 += tl[j];

        // high-bit parity groups (h = msk >> 5)
        float U1 = tl[5] + tl[13];   // 0x30, 0x28  (h=1)
        float U2 = tl[14];           // 0x50        (h=2)
        float U3 = tl[6];            // 0x60        (h=3)
        float U5 = tl[15];           // 0xA0        (h=5)
        float U6 = tl[7];            // 0xC0        (h=6)

        float F[8];
        F[0] = 0.0f;
        F[1] = U1 + U3 + U5;
        F[2] = U2 + U3 + U6;
        F[3] = U1 + U2 + U5 + U6;
        F[4] = U5 + U6;
        F[5] = U1 + U3 + U6;
        F[6] = U2 + U3 + U5;
        F[7] = U1 + U2;

        float C[8];
#pragma unroll
        for (int r = 0; r < 8; r++)
            C[r] = __cosf(fmaf(-2.0f, F[r], d0));

        // FWHT over w bits 5..7 (register butterflies)
#pragma unroll
        for (int sb = 1; sb < 8; sb <<= 1) {
            float t[8];
#pragma unroll
            for (int r = 0; r < 8; r++)
                t[r] = (r & sb) ? (C[r ^ sb] - C[r]) : (C[r] + C[r ^ sb]);
#pragma unroll
            for (int r = 0; r < 8; r++) C[r] = t[r];
        }
        // FWHT over w bits 0..4 (shuffle butterflies)
#pragma unroll
        for (int s = 1; s < 32; s <<= 1) {
            float sign = (lane & s) ? -1.0f : 1.0f;
#pragma unroll
            for (int r = 0; r < 8; r++) {
                float o = __shfl_xor_sync(FULL, C[r], s);
                C[r] = fmaf(sign, C[r], o);
            }
        }
#pragma unroll
        for (int r = 0; r < 8; r++)
            sD[i][r * 32 + lane] = C[r] * (1.0f / 256.0f);
    }
    __syncthreads();

    if (role == 0) {
        // ---- eval out0-4 (registers + sD only; identical math to R9-R14) ----
        float o0 = cz0 * fmaf(sD[0][0x60], sz2 * sz1, sD[0][0x00]);

        float o1 = fmaf(sD[1][0xA0], sz2 * sz0, sD[1][0x00]);
        o1 = fmaf(sD[1][0x30], sz3 * sz2, o1);
        o1 = fmaf(sD[1][0x90], sz3 * sz0, o1);
        o1 *= cz1;

        float o2 = fmaf(sD[2][0x50], sz3 * sz1, sD[2][0x00]);
        o2 = fmaf(sD[2][0x18], sz4 * sz3, o2);
        o2 = fmaf(sD[2][0x48], sz4 * sz1, o2);
        o2 *= cz0 * cz2;

        float s0C = sz5 * sz4, s20 = sz2 * sz0;
        float o3 = fmaf(sD[3][0x28], sz4 * sz2, sD[3][0x00]);
        o3 = fmaf(sD[3][0x0C], s0C, o3);
        o3 = fmaf(sD[3][0x24], sz5 * sz2, o3);
        o3 = fmaf(sD[3][0xA0], s20, o3);
        o3 = fmaf(sD[3][0x84], sz5 * sz0, o3);
        o3 = fmaf(sD[3][0xAC], s0C * s20, o3);
        o3 = fmaf(sD[3][0x88], sz4 * sz0, o3);
        o3 *= cz1 * cz3;

        // out4: comp(0xA8); inner sz7,sz6,sz5; outer p4 = {1,sz3,sz1,sz3*sz1}
        float p4[4] = {1.0f, sz3, sz1, sz3 * sz1};
        const int b4[4] = {0, 16, 64, 80};
        float acc4 = 0.0f;
#pragma unroll
        for (int g = 0; g < 4; g++) {
            float4 a = *reinterpret_cast<const float4*>(&sD[4][b4[g]]);
            float4 b = *reinterpret_cast<const float4*>(&sD[4][b4[g] + 4]);
            float lo = fmaf(a.y, sz7, a.x) + sz6 * fmaf(a.w, sz7, a.z);
            float hi = fmaf(b.y, sz7, b.x) + sz6 * fmaf(b.w, sz7, b.z);
            acc4 = fmaf(p4[g], fmaf(sz5, hi, lo), acc4);
        }
        float o4 = (cz0 * cz2 * cz4) * acc4;

        *reinterpret_cast<float4*>(out + e * 8) = make_float4(o0, o1, o2, o3);
        out[e * 8 + 4] = o4;
    } else {
        // ---- eval out5-7 from published sincos (identical math to R9-R14) ----
        const float a0 = s_sz[0][eloc], a1 = s_sz[1][eloc];
        const float a2 = s_sz[2][eloc], a3 = s_sz[3][eloc];
        const float a4 = s_sz[4][eloc], a5 = s_sz[5][eloc];
        const float a6 = s_sz[6][eloc], a7 = s_sz[7][eloc];
        const float K5 = s_K[0][eloc], K6 = s_K[1][eloc], K7 = s_K[2][eloc];

        float s42 = a4 * a2, s40 = a4 * a0, s20 = a2 * a0, s420 = s42 * a0;
        float m53 = a5 * a3, m51 = a5 * a1, m31 = a3 * a1, m531 = m53 * a1;
        float p8[8] = {1.0f, a4, a2, s42, a0, s40, s20, s420};
        float p6[8] = {1.0f, a5, a3, m53, a1, m51, m31, m531};

        const int b5[8] = {0, 8, 32, 40, 128, 136, 160, 168};
        float acc5 = 0.0f;
#pragma unroll
        for (int g = 0; g < 8; g++) {
            float4 a = *reinterpret_cast<const float4*>(&sD[5][b5[g]]);
            float inner = fmaf(a.y, a7, a.x) + a6 * fmaf(a.w, a7, a.z);
            acc5 = fmaf(p8[g], inner, acc5);
        }
        const int b6[8] = {0, 4, 16, 20, 64, 68, 80, 84};
        float acc6 = 0.0f;
#pragma unroll
        for (int g = 0; g < 8; g++) {
            float2 a = *reinterpret_cast<const float2*>(&sD[6][b6[g]]);
            acc6 = fmaf(p6[g], fmaf(a.y, a7, a.x), acc6);
        }
        float acc7 = 0.0f;
#pragma unroll
        for (int g = 0; g < 8; g++) {
            float lo = sD[7][b5[g]];
            float hi = sD[7][b5[g] + 2];
            acc7 = fmaf(p8[g], fmaf(hi, a6, lo), acc7);
        }

        out[e * 8 + 5] = K5 * acc5;
        *reinterpret_cast<float2*>(out + e * 8 + 6) = make_float2(K6 * acc6, K7 * acc7);
    }
}

extern "C" void kernel_launch(void* const* d_in, const int* in_sizes, int n_in,
                              void* d_out, int out_size) {
    const float* inputs  = (const float*)d_in[0];   // (32768, 8) float32
    const float* weights = (const float*)d_in[1];   // (2, 8)     float32
    float* out = (float*)d_out;                     // (32768, 8) float32

    // 128 blocks x 512 threads (R11 geometry): warps 0-7 sincos+eval0-4,
    // warps 8-15 FWHT+eval5-7; delta phase computed incrementally
    vqc_fused<<<BATCH / 256, 512>>>(inputs, weights, out);
}

// round 16
// speedup vs baseline: 1.0531x; 1.0386x over previous
#include <cuda_runtime.h>

#define FULL 0xffffffffu
#define BATCH 32768

// Fused VQC (math validated R7-R15): out_i = K_i * sum_T D_i[T] * sigma_T.
// R16 = R15 with the full __syncthreads() replaced by two one-directional
// named barriers (producer -> consumer):
//   barrier 1: role 1 arrives after writing sD;      role 0 syncs on it.
//   barrier 2: role 0 arrives after publishing sz/K; role 1 syncs on it.
// Each role arrives before it syncs -> deadlock-free; counts = 512.
// Critical path: max(pre0+post1, pre1+post0) instead of max(pre)+max(post).

__global__ __launch_bounds__(512) void vqc_fused(const float* __restrict__ inputs,
                                                 const float* __restrict__ weights,
                                                 float* __restrict__ out) {
    __shared__ float sD[8][256];
    __shared__ float s_sz[8][256];
    __shared__ float s_K[3][256];

    const int tid  = threadIdx.x;
    const int lane = tid & 31;
    const int wid  = tid >> 5;
    const int role = tid >> 8;          // warp-uniform
    const int eloc = tid & 255;
    const int e    = blockIdx.x * 256 + eloc;

    if (role == 0) {
        // ---- full-element sincos pipeline ----
        float sz0, cz0, sz1, cz1, sz2, cz2, sz3, cz3;
        float sz4, cz4, sz5, cz5, sz6, cz6, sz7, cz7;
        const float4 z0 = *reinterpret_cast<const float4*>(inputs + e * 8);
        const float4 z1 = *reinterpret_cast<const float4*>(inputs + e * 8 + 4);
        __sincosf(z0.x, &sz0, &cz0);  __sincosf(z0.y, &sz1, &cz1);
        __sincosf(z0.z, &sz2, &cz2);  __sincosf(z0.w, &sz3, &cz3);
        __sincosf(z1.x, &sz4, &cz4);  __sincosf(z1.y, &sz5, &cz5);
        __sincosf(z1.z, &sz6, &cz6);  __sincosf(z1.w, &sz7, &cz7);

        s_sz[0][eloc] = sz0; s_sz[1][eloc] = sz1; s_sz[2][eloc] = sz2; s_sz[3][eloc] = sz3;
        s_sz[4][eloc] = sz4; s_sz[5][eloc] = sz5; s_sz[6][eloc] = sz6; s_sz[7][eloc] = sz7;

        float K5 = cz1 * cz3 * cz5;
        float K6 = cz0 * cz2 * cz4 * cz6;
        float K7 = K5 * cz7;
        s_K[0][eloc] = K5; s_K[1][eloc] = K6; s_K[2][eloc] = K7;

        // publish done -> let role 1 proceed; then wait for sD
        asm volatile("bar.arrive 2, 512;" ::: "memory");
        asm volatile("bar.sync 1, 512;" ::: "memory");

        // ---- eval out0-4 (registers + sD only; identical math to R9-R15) ----
        float o0 = cz0 * fmaf(sD[0][0x60], sz2 * sz1, sD[0][0x00]);

        float o1 = fmaf(sD[1][0xA0], sz2 * sz0, sD[1][0x00]);
        o1 = fmaf(sD[1][0x30], sz3 * sz2, o1);
        o1 = fmaf(sD[1][0x90], sz3 * sz0, o1);
        o1 *= cz1;

        float o2 = fmaf(sD[2][0x50], sz3 * sz1, sD[2][0x00]);
        o2 = fmaf(sD[2][0x18], sz4 * sz3, o2);
        o2 = fmaf(sD[2][0x48], sz4 * sz1, o2);
        o2 *= cz0 * cz2;

        float s0C = sz5 * sz4, s20 = sz2 * sz0;
        float o3 = fmaf(sD[3][0x28], sz4 * sz2, sD[3][0x00]);
        o3 = fmaf(sD[3][0x0C], s0C, o3);
        o3 = fmaf(sD[3][0x24], sz5 * sz2, o3);
        o3 = fmaf(sD[3][0xA0], s20, o3);
        o3 = fmaf(sD[3][0x84], sz5 * sz0, o3);
        o3 = fmaf(sD[3][0xAC], s0C * s20, o3);
        o3 = fmaf(sD[3][0x88], sz4 * sz0, o3);
        o3 *= cz1 * cz3;

        // out4: comp(0xA8); inner sz7,sz6,sz5; outer p4 = {1,sz3,sz1,sz3*sz1}
        float p4[4] = {1.0f, sz3, sz1, sz3 * sz1};
        const int b4[4] = {0, 16, 64, 80};
        float acc4 = 0.0f;
#pragma unroll
        for (int g = 0; g < 4; g++) {
            float4 a = *reinterpret_cast<const float4*>(&sD[4][b4[g]]);
            float4 b = *reinterpret_cast<const float4*>(&sD[4][b4[g] + 4]);
            float lo = fmaf(a.y, sz7, a.x) + sz6 * fmaf(a.w, sz7, a.z);
            float hi = fmaf(b.y, sz7, b.x) + sz6 * fmaf(b.w, sz7, b.z);
            acc4 = fmaf(p4[g], fmaf(sz5, hi, lo), acc4);
        }
        float o4 = (cz0 * cz2 * cz4) * acc4;

        *reinterpret_cast<float4*>(out + e * 8) = make_float4(o0, o1, o2, o3);
        out[e * 8 + 4] = o4;
    } else {
        // ---- FWHT pipeline: warp (wid-8) builds table D_(wid-8) ----
        const int i  = wid - 8;
        const int sh = 6 - 2 * (i >> 1);
        const int A  = (((0xAA >> sh) << sh) >> (i & 1));
        const int msk[16]  = {0x01,0x03,0x06,0x0C,0x18,0x30,0x60,0xC0,
                              0x01,0x02,0x05,0x0A,0x14,0x28,0x50,0xA0};
        const int widx[16] = {7,6,5,4,3,2,1,0, 15,14,13,12,11,10,9,8};

        // tl[j] = (j in S_i) ? eps_j(lane)*theta_j : 0   (validated R15)
        float tl[16];
#pragma unroll
        for (int j = 0; j < 16; j++) {
            float th = __ldg(&weights[widx[j]]);
            bool inS = (__popc(msk[j] & A) & 1);             // warp-uniform
            float v  = (__popc(msk[j] & lane) & 1) ? -th : th;
            tl[j] = inS ? v : 0.0f;
        }
        float d0 = 0.0f;
#pragma unroll
        for (int j = 0; j < 16; j++) d0 += tl[j];

        float U1 = tl[5] + tl[13];
        float U2 = tl[14];
        float U3 = tl[6];
        float U5 = tl[15];
        float U6 = tl[7];

        float F[8];
        F[0] = 0.0f;
        F[1] = U1 + U3 + U5;
        F[2] = U2 + U3 + U6;
        F[3] = U1 + U2 + U5 + U6;
        F[4] = U5 + U6;
        F[5] = U1 + U3 + U6;
        F[6] = U2 + U3 + U5;
        F[7] = U1 + U2;

        float C[8];
#pragma unroll
        for (int r = 0; r < 8; r++)
            C[r] = __cosf(fmaf(-2.0f, F[r], d0));

#pragma unroll
        for (int sb = 1; sb < 8; sb <<= 1) {
            float t[8];
#pragma unroll
            for (int r = 0; r < 8; r++)
                t[r] = (r & sb) ? (C[r ^ sb] - C[r]) : (C[r] + C[r ^ sb]);
#pragma unroll
            for (int r = 0; r < 8; r++) C[r] = t[r];
        }
#pragma unroll
        for (int s = 1; s < 32; s <<= 1) {
            float sign = (lane & s) ? -1.0f : 1.0f;
#pragma unroll
            for (int r = 0; r < 8; r++) {
                float o = __shfl_xor_sync(FULL, C[r], s);
                C[r] = fmaf(sign, C[r], o);
            }
        }
#pragma unroll
        for (int r = 0; r < 8; r++)
            sD[i][r * 32 + lane] = C[r] * (1.0f / 256.0f);

        // sD done -> let role 0 proceed; then wait for published sincos
        asm volatile("bar.arrive 1, 512;" ::: "memory");
        asm volatile("bar.sync 2, 512;" ::: "memory");

        // ---- eval out5-7 from published sincos (identical math to R9-R15) ----
        const float a0 = s_sz[0][eloc], a1 = s_sz[1][eloc];
        const float a2 = s_sz[2][eloc], a3 = s_sz[3][eloc];
        const float a4 = s_sz[4][eloc], a5 = s_sz[5][eloc];
        const float a6 = s_sz[6][eloc], a7 = s_sz[7][eloc];
        const float K5 = s_K[0][eloc], K6 = s_K[1][eloc], K7 = s_K[2][eloc];

        float s42 = a4 * a2, s40 = a4 * a0, s20 = a2 * a0, s420 = s42 * a0;
        float m53 = a5 * a3, m51 = a5 * a1, m31 = a3 * a1, m531 = m53 * a1;
        float p8[8] = {1.0f, a4, a2, s42, a0, s40, s20, s420};
        float p6[8] = {1.0f, a5, a3, m53, a1, m51, m31, m531};

        const int b5[8] = {0, 8, 32, 40, 128, 136, 160, 168};
        float acc5 = 0.0f;
#pragma unroll
        for (int g = 0; g < 8; g++) {
            float4 a = *reinterpret_cast<const float4*>(&sD[5][b5[g]]);
            float inner = fmaf(a.y, a7, a.x) + a6 * fmaf(a.w, a7, a.z);
            acc5 = fmaf(p8[g], inner, acc5);
        }
        const int b6[8] = {0, 4, 16, 20, 64, 68, 80, 84};
        float acc6 = 0.0f;
#pragma unroll
        for (int g = 0; g < 8; g++) {
            float2 a = *reinterpret_cast<const float2*>(&sD[6][b6[g]]);
            acc6 = fmaf(p6[g], fmaf(a.y, a7, a.x), acc6);
        }
        float acc7 = 0.0f;
#pragma unroll
        for (int g = 0; g < 8; g++) {
            float lo = sD[7][b5[g]];
            float hi = sD[7][b5[g] + 2];
            acc7 = fmaf(p8[g], fmaf(hi, a6, lo), acc7);
        }

        out[e * 8 + 5] = K5 * acc5;
        *reinterpret_cast<float2*>(out + e * 8 + 6) = make_float2(K6 * acc6, K7 * acc7);
    }
}

extern "C" void kernel_launch(void* const* d_in, const int* in_sizes, int n_in,
                              void* d_out, int out_size) {
    const float* inputs  = (const float*)d_in[0];   // (32768, 8) float32
    const float* weights = (const float*)d_in[1];   // (2, 8)     float32
    float* out = (float*)d_out;                     // (32768, 8) float32

    // 128 blocks x 512 threads: warps 0-7 sincos+eval0-4, warps 8-15
    // FWHT+eval5-7; split producer->consumer named barriers
    vqc_fused<<<BATCH / 256, 512>>>(inputs, weights, out);
}